// round 14
// baseline (speedup 1.0000x reference)
#include <cuda_runtime.h>
#include <cuda_fp16.h>

#define NN 50000
#define NE 800000
#define TE (NE + NN)
#define H  5
#define C1 32
#define F1 160
#define NF 5

// ---------------- device scratch ---------------------------------------------
__device__ __half g_h1h[NN * F1];    // layer1 node features, fp16 [N,160] (320B rows)
__device__ float  g_as1p[NN * 8];    // alpha_src layer1, padded to 8
__device__ float  g_ad1[NN * H];     // alpha_dst layer1
__device__ float  g_h2p[NN * 8];     // layer2 node features, padded to 8
__device__ int    g_cnt[NN];         // in-degree counts (zeroed by k_alloc each call)
__device__ int    g_beg[NN];         // segment begin
__device__ int    g_end[NN];         // segment end
__device__ int    g_cur[NN];         // scatter cursors
__device__ int2   g_ep[TE];          // packed (src, edge_attr), grouped by dst
__device__ int    g_total;           // atomic allocation base
__device__ float  g_easum;
__device__ float  g_eamean;
__device__ float  g_wed1[H];
__device__ float  g_wed2[H];

__device__ __forceinline__ float lrelu(float x) { return x > 0.f ? x : 0.2f * x; }

// ---------------- fused front: node1 transform (warp/node) + count + easum ---
__global__ void __launch_bounds__(256) k_front(
        const float* __restrict__ x, const float* __restrict__ W1,
        const float* __restrict__ as, const float* __restrict__ ad,
        const int* __restrict__ dst, const float* __restrict__ ea,
        int N, int E, int nbN) {
    int b = blockIdx.x, t = threadIdx.x;
    if (b == 0 && t == 0) g_total = 0;
    if (b < nbN) {
        int n = b * 8 + (t >> 5);
        int lane = t & 31;
        if (n >= N) return;
        float xv[NF];
        #pragma unroll
        for (int f = 0; f < NF; f++) xv[f] = __ldg(&x[n * NF + f]);
        #pragma unroll
        for (int h = 0; h < H; h++) {
            int c = h * C1 + lane;
            float v = 0.f;
            #pragma unroll
            for (int f = 0; f < NF; f++) v = fmaf(xv[f], __ldg(&W1[f * F1 + c]), v);
            g_h1h[n * F1 + c] = __float2half(v);
            float s = v * __ldg(&as[c]);
            float d = v * __ldg(&ad[c]);
            #pragma unroll
            for (int o = 16; o > 0; o >>= 1) {
                s += __shfl_xor_sync(0xffffffffu, s, o);
                d += __shfl_xor_sync(0xffffffffu, d, o);
            }
            if (lane == 0) { g_as1p[n * 8 + h] = s; g_ad1[n * H + h] = d; }
        }
    } else {
        __shared__ float sh[256];
        int i = (b - nbN) * 256 + t;
        float v = 0.f;
        if (i < E) { atomicAdd(&g_cnt[dst[i]], 1); v = ea[i]; }
        sh[t] = v;
        __syncthreads();
        for (int o = 128; o > 0; o >>= 1) {
            if (t < o) sh[t] += sh[t + o];
            __syncthreads();
        }
        if (t == 0) atomicAdd(&g_easum, sh[0]);
    }
}

// ---------------- segment allocation: block scan + atomic base ---------------
__global__ void __launch_bounds__(256) k_alloc(
        const float* __restrict__ We1, const float* __restrict__ ae1,
        const float* __restrict__ We2, const float* __restrict__ ae2,
        int N, int E) {
    __shared__ int ws[8], wo[8];
    __shared__ int sbase;
    int b = blockIdx.x, t = threadIdx.x, lane = t & 31, w = t >> 5;
    int i = b * 256 + t;
    int v = (i < N) ? (g_cnt[i] + 1) : 0;   // +1 = self loop
    int sv = v;
    #pragma unroll
    for (int o = 1; o < 32; o <<= 1) {
        int u = __shfl_up_sync(0xffffffffu, sv, o);
        if (lane >= o) sv += u;
    }
    if (lane == 31) ws[w] = sv;
    __syncthreads();
    if (t < 8) {
        int acc = 0;
        for (int j = 0; j < t; j++) acc += ws[j];
        wo[t] = acc;
    }
    __syncthreads();
    if (t == 0) sbase = atomicAdd(&g_total, wo[7] + ws[7]);
    __syncthreads();
    if (i < N) {
        int beg = sbase + wo[w] + sv - v;
        g_beg[i] = beg; g_end[i] = beg + v; g_cur[i] = beg;
        g_cnt[i] = 0;                        // reset for next call
    }
    if (b == 0) {
        if (t < H) {
            float a = 0.f;
            for (int c = 0; c < C1; c++) a += We1[t * C1 + c] * ae1[t * C1 + c];
            g_wed1[t] = a;
            g_wed2[t] = We2[t] * ae2[t];
        }
        if (t == 0) { g_eamean = g_easum / (float)E; g_easum = 0.f; }
    }
}

// ---------------- scatter into packed segments -------------------------------
__global__ void k_scatter(const int* __restrict__ src, const int* __restrict__ dst,
                          const float* __restrict__ ea, int E, int N) {
    int i = blockIdx.x * blockDim.x + threadIdx.x;
    if (i < E) {
        int p = atomicAdd(&g_cur[dst[i]], 1);
        g_ep[p] = make_int2(src[i], __float_as_int(ea[i]));
    } else if (i < E + N) {
        int n = i - E;
        int p = atomicAdd(&g_cur[n], 1);
        g_ep[p] = make_int2(n, __float_as_int(g_eamean));
    }
}

// ---------------- layer 1 aggregation: warp per dst --------------------------
// Gather restructured for L1 wavefronts: ONE LDG.128 per edge (lane<20 loads
// 8 fp16 channels = full 320B row per warp-load). Attention weight per lane
// comes from a per-warp smem staging buffer (1 broadcast LDS, replaces 5 SHFL).
// Softmax without max-shift (logits O(1)-bounded). Fused relu + node2 epilogue.
__global__ void __launch_bounds__(256) k_agg1(const float* __restrict__ b1,
                                              const float* __restrict__ W2, int N) {
    __shared__ float exbuf[8][32][H];        // [warp][edge-in-tile][head]
    int gt = blockIdx.x * blockDim.x + threadIdx.x;
    int d = gt >> 5, lane = gt & 31;
    int w = (threadIdx.x >> 5);
    if (d >= N) return;
    int beg = g_beg[d], end = g_end[d];
    float adh[H], we[H];
    #pragma unroll
    for (int h = 0; h < H; h++) { adh[h] = g_ad1[d * H + h]; we[h] = g_wed1[h]; }

    const bool active = lane < 20;           // 20 lanes x 8 halves = 160 channels
    int head = lane >> 2;                    // 8 consecutive ch stay in one head
    const float* exp_rd = &exbuf[w][0][0];   // read ex at [j*H + head]

    float sm[H] = {0, 0, 0, 0, 0};
    float acc[8] = {0, 0, 0, 0, 0, 0, 0, 0};

    for (int t0 = beg; t0 < end; t0 += 32) {
        int e = t0 + lane;
        int s = 0;
        float ex[H];
        if (e < end) {
            int2 pv = __ldg(&g_ep[e]);
            s = pv.x;
            float eav = __int_as_float(pv.y);
            const float4* ap = (const float4*)&g_as1p[s * 8];
            float4 a0 = __ldg(ap);
            float4 a1 = __ldg(ap + 1);
            float av[H] = {a0.x, a0.y, a0.z, a0.w, a1.x};
            #pragma unroll
            for (int h = 0; h < H; h++) {
                ex[h] = __expf(lrelu(av[h] + adh[h] + eav * we[h]));
                sm[h] += ex[h];
            }
        } else {
            #pragma unroll
            for (int h = 0; h < H; h++) ex[h] = 0.f;
        }
        #pragma unroll
        for (int h = 0; h < H; h++) exbuf[w][lane][h] = ex[h];
        __syncwarp();

        int cnt = min(32, end - t0);
        for (int j = 0; j < cnt; j++) {
            int s2 = __shfl_sync(0xffffffffu, s, j);
            if (active) {
                float a = exp_rd[j * H + head];           // broadcast LDS
                uint4 hr = *(const uint4*)&g_h1h[s2 * F1 + lane * 8]; // 1 LDG.128
                float2 f0 = __half22float2(*(const __half2*)&hr.x);
                float2 f1 = __half22float2(*(const __half2*)&hr.y);
                float2 f2 = __half22float2(*(const __half2*)&hr.z);
                float2 f3 = __half22float2(*(const __half2*)&hr.w);
                acc[0] = fmaf(a, f0.x, acc[0]);
                acc[1] = fmaf(a, f0.y, acc[1]);
                acc[2] = fmaf(a, f1.x, acc[2]);
                acc[3] = fmaf(a, f1.y, acc[3]);
                acc[4] = fmaf(a, f2.x, acc[4]);
                acc[5] = fmaf(a, f2.y, acc[5]);
                acc[6] = fmaf(a, f3.x, acc[6]);
                acc[7] = fmaf(a, f3.y, acc[7]);
            }
        }
        __syncwarp();
    }
    #pragma unroll
    for (int h = 0; h < H; h++)
        #pragma unroll
        for (int o = 16; o > 0; o >>= 1)
            sm[h] += __shfl_xor_sync(0xffffffffu, sm[h], o);

    // epilogue: lane (l<20) owns channels c0=8l..8l+7 (all in head l>>2)
    float hv[H] = {0, 0, 0, 0, 0};
    if (active) {
        float inv = 1.f / (sm[head] + 1e-16f);
        int c0 = lane * 8;
        #pragma unroll
        for (int k = 0; k < 8; k++) {
            float xo = fmaxf(acc[k] * inv + __ldg(&b1[c0 + k]), 0.f);
            const float* wr = &W2[(c0 + k) * H];
            #pragma unroll
            for (int h2 = 0; h2 < H; h2++) hv[h2] = fmaf(xo, __ldg(&wr[h2]), hv[h2]);
        }
    }
    #pragma unroll
    for (int h2 = 0; h2 < H; h2++)
        #pragma unroll
        for (int o = 16; o > 0; o >>= 1)
            hv[h2] += __shfl_xor_sync(0xffffffffu, hv[h2], o);
    float wv = (lane == 0) ? hv[0] : (lane == 1) ? hv[1] : (lane == 2) ? hv[2]
             : (lane == 3) ? hv[3] : (lane == 4) ? hv[4] : 0.f;
    if (lane < 8) g_h2p[d * 8 + lane] = wv;   // padded row, zeros in 5..7
}

// ---------------- layer 2 aggregation + head-mean + linear + sigmoid ---------
__global__ void __launch_bounds__(256) k_agg2(
        const float* __restrict__ as2p, const float* __restrict__ ad2p,
        const float* __restrict__ b2, const float* __restrict__ Wlin,
        float* __restrict__ out, int N) {
    int gt = blockIdx.x * blockDim.x + threadIdx.x;
    int d = gt >> 5, lane = gt & 31;
    if (d >= N) return;
    int beg = g_beg[d], end = g_end[d];
    const float4* dp = (const float4*)&g_h2p[d * 8];
    float4 q0 = __ldg(dp), q1 = __ldg(dp + 1);
    float hd[H] = {q0.x, q0.y, q0.z, q0.w, q1.x};
    float adh[H], as2[H], we[H];
    #pragma unroll
    for (int h = 0; h < H; h++) {
        adh[h] = hd[h] * __ldg(&ad2p[h]);
        as2[h] = __ldg(&as2p[h]);
        we[h] = g_wed2[h];
    }
    float sm[H] = {0, 0, 0, 0, 0}, ws[H] = {0, 0, 0, 0, 0};
    for (int e = beg + lane; e < end; e += 32) {
        int2 pv = __ldg(&g_ep[e]);
        float eav = __int_as_float(pv.y);
        const float4* sp = (const float4*)&g_h2p[pv.x * 8];
        float4 p0 = __ldg(sp), p1 = __ldg(sp + 1);
        float hs[H] = {p0.x, p0.y, p0.z, p0.w, p1.x};
        #pragma unroll
        for (int h = 0; h < H; h++) {
            float ex = __expf(lrelu(hs[h] * as2[h] + adh[h] + eav * we[h]));
            sm[h] += ex;
            ws[h] = fmaf(ex, hs[h], ws[h]);
        }
    }
    #pragma unroll
    for (int h = 0; h < H; h++)
        #pragma unroll
        for (int o = 16; o > 0; o >>= 1) {
            sm[h] += __shfl_xor_sync(0xffffffffu, sm[h], o);
            ws[h] += __shfl_xor_sync(0xffffffffu, ws[h], o);
        }
    if (lane == 0) {
        float m = 0.f;
        #pragma unroll
        for (int h = 0; h < H; h++) m += ws[h] / (sm[h] + 1e-16f);
        m = m * 0.2f + __ldg(&b2[0]);
        m *= __ldg(&Wlin[0]);
        out[d] = 1.f / (1.f + __expf(-m));
    }
}

// ---------------- launch -----------------------------------------------------
extern "C" void kernel_launch(void* const* d_in, const int* in_sizes, int n_in,
                              void* d_out, int out_size) {
    const float* x     = (const float*)d_in[0];
    const float* eattr = (const float*)d_in[1];
    const int*   src   = (const int*)  d_in[2];
    const int*   dst   = (const int*)  d_in[3];
    const float* W1    = (const float*)d_in[4];
    const float* as1   = (const float*)d_in[5];
    const float* ad1   = (const float*)d_in[6];
    const float* We1   = (const float*)d_in[7];
    const float* ae1   = (const float*)d_in[8];
    const float* b1    = (const float*)d_in[9];
    const float* W2    = (const float*)d_in[10];
    const float* as2   = (const float*)d_in[11];
    const float* ad2   = (const float*)d_in[12];
    const float* We2   = (const float*)d_in[13];
    const float* ae2   = (const float*)d_in[14];
    const float* b2    = (const float*)d_in[15];
    const float* Wlin  = (const float*)d_in[16];
    float* out = (float*)d_out;

    int N = in_sizes[0] / NF;
    int E = in_sizes[2];
    int nbN = (N + 7) / 8;
    int nbE = (E + 255) / 256;

    k_front  <<<nbN + nbE, 256>>>(x, W1, as1, ad1, dst, eattr, N, E, nbN);
    k_alloc  <<<(N + 255) / 256, 256>>>(We1, ae1, We2, ae2, N, E);
    k_scatter<<<(E + N + 255) / 256, 256>>>(src, dst, eattr, E, N);
    k_agg1   <<<(N * 32 + 255) / 256, 256>>>(b1, W2, N);
    k_agg2   <<<(N * 32 + 255) / 256, 256>>>(as2, ad2, b2, Wlin, out, N);
}

// round 15
// speedup vs baseline: 1.1736x; 1.1736x over previous
#include <cuda_runtime.h>
#include <cuda_fp16.h>

#define NN 50000
#define NE 800000
#define TE (NE + NN)
#define H  5
#define C1 32
#define F1 160
#define NF 5

// ---------------- device scratch ---------------------------------------------
// h1 transposed+padded: [node][lane(32)][head(5)+3pad] fp16 -> 512B/row, aligned.
// lane l's 5 channels (c = h*32+l) are contiguous -> ONE LDG.128 per edge.
__device__ __half g_h1t[NN * 256];
__device__ float  g_as1p[NN * 8];    // alpha_src layer1, padded to 8
__device__ float  g_ad1[NN * H];     // alpha_dst layer1
__device__ float  g_h2p[NN * 8];     // layer2 node features, padded to 8
__device__ int    g_cnt[NN];         // in-degree counts (zeroed by k_alloc each call)
__device__ int    g_beg[NN];         // segment begin
__device__ int    g_end[NN];         // segment end
__device__ int    g_cur[NN];         // scatter cursors
__device__ int2   g_ep[TE];          // packed (src, edge_attr), grouped by dst
__device__ int    g_total;           // atomic allocation base
__device__ float  g_easum;
__device__ float  g_eamean;
__device__ float  g_wed1[H];
__device__ float  g_wed2[H];

__device__ __forceinline__ float lrelu(float x) { return x > 0.f ? x : 0.2f * x; }

// ---------------- fused front: node1 transform (warp/node) + count + easum ---
__global__ void __launch_bounds__(256) k_front(
        const float* __restrict__ x, const float* __restrict__ W1,
        const float* __restrict__ as, const float* __restrict__ ad,
        const int* __restrict__ dst, const float* __restrict__ ea,
        int N, int E, int nbN) {
    int b = blockIdx.x, t = threadIdx.x;
    if (b == 0 && t == 0) g_total = 0;
    if (b < nbN) {
        int n = b * 8 + (t >> 5);
        int lane = t & 31;
        if (n >= N) return;
        float xv[NF];
        #pragma unroll
        for (int f = 0; f < NF; f++) xv[f] = __ldg(&x[n * NF + f]);
        float v[H];
        #pragma unroll
        for (int h = 0; h < H; h++) {
            int c = h * C1 + lane;
            float vv = 0.f;
            #pragma unroll
            for (int f = 0; f < NF; f++) vv = fmaf(xv[f], __ldg(&W1[f * F1 + c]), vv);
            v[h] = vv;
            float s = vv * __ldg(&as[c]);
            float d = vv * __ldg(&ad[c]);
            #pragma unroll
            for (int o = 16; o > 0; o >>= 1) {
                s += __shfl_xor_sync(0xffffffffu, s, o);
                d += __shfl_xor_sync(0xffffffffu, d, o);
            }
            if (lane == 0) { g_as1p[n * 8 + h] = s; g_ad1[n * H + h] = d; }
        }
        // pack lane's 5 head-values into one 16B slot -> single ST.128
        union { __half hh[8]; uint4 u; } pk;
        #pragma unroll
        for (int h = 0; h < H; h++) pk.hh[h] = __float2half(v[h]);
        pk.hh[5] = __ushort_as_half((unsigned short)0);
        pk.hh[6] = __ushort_as_half((unsigned short)0);
        pk.hh[7] = __ushort_as_half((unsigned short)0);
        *(uint4*)&g_h1t[n * 256 + lane * 8] = pk.u;
    } else {
        __shared__ float sh[256];
        int i = (b - nbN) * 256 + t;
        float v = 0.f;
        if (i < E) { atomicAdd(&g_cnt[dst[i]], 1); v = ea[i]; }
        sh[t] = v;
        __syncthreads();
        for (int o = 128; o > 0; o >>= 1) {
            if (t < o) sh[t] += sh[t + o];
            __syncthreads();
        }
        if (t == 0) atomicAdd(&g_easum, sh[0]);
    }
}

// ---------------- segment allocation: block scan + atomic base ---------------
__global__ void __launch_bounds__(256) k_alloc(
        const float* __restrict__ We1, const float* __restrict__ ae1,
        const float* __restrict__ We2, const float* __restrict__ ae2,
        int N, int E) {
    __shared__ int ws[8], wo[8];
    __shared__ int sbase;
    int b = blockIdx.x, t = threadIdx.x, lane = t & 31, w = t >> 5;
    int i = b * 256 + t;
    int v = (i < N) ? (g_cnt[i] + 1) : 0;   // +1 = self loop
    int sv = v;
    #pragma unroll
    for (int o = 1; o < 32; o <<= 1) {
        int u = __shfl_up_sync(0xffffffffu, sv, o);
        if (lane >= o) sv += u;
    }
    if (lane == 31) ws[w] = sv;
    __syncthreads();
    if (t < 8) {
        int acc = 0;
        for (int j = 0; j < t; j++) acc += ws[j];
        wo[t] = acc;
    }
    __syncthreads();
    if (t == 0) sbase = atomicAdd(&g_total, wo[7] + ws[7]);
    __syncthreads();
    if (i < N) {
        int beg = sbase + wo[w] + sv - v;
        g_beg[i] = beg; g_end[i] = beg + v; g_cur[i] = beg;
        g_cnt[i] = 0;                        // reset for next call
    }
    if (b == 0) {
        if (t < H) {
            float a = 0.f;
            for (int c = 0; c < C1; c++) a += We1[t * C1 + c] * ae1[t * C1 + c];
            g_wed1[t] = a;
            g_wed2[t] = We2[t] * ae2[t];
        }
        if (t == 0) { g_eamean = g_easum / (float)E; g_easum = 0.f; }
    }
}

// ---------------- scatter into packed segments -------------------------------
__global__ void k_scatter(const int* __restrict__ src, const int* __restrict__ dst,
                          const float* __restrict__ ea, int E, int N) {
    int i = blockIdx.x * blockDim.x + threadIdx.x;
    if (i < E) {
        int p = atomicAdd(&g_cur[dst[i]], 1);
        g_ep[p] = make_int2(src[i], __float_as_int(ea[i]));
    } else if (i < E + N) {
        int n = i - E;
        int p = atomicAdd(&g_cur[n], 1);
        g_ep[p] = make_int2(n, __float_as_int(g_eamean));
    }
}

// ---------------- layer 1 aggregation: warp per dst --------------------------
// R12 structure (SHFL broadcast — shared staging proved worse, R14) but the
// gather is now ONE coalesced LDG.128 per edge from the transposed h1 layout:
// lane l gets its 5 head-channels (c=h*32+l) in one 16B load. Softmax without
// max-shift (logits O(1)-bounded). Fused relu + node2 (h2=relu(x1)@W2) epilogue.
__global__ void __launch_bounds__(256) k_agg1(const float* __restrict__ b1,
                                              const float* __restrict__ W2, int N) {
    int gt = blockIdx.x * blockDim.x + threadIdx.x;
    int d = gt >> 5, lane = gt & 31;
    if (d >= N) return;
    int beg = g_beg[d], end = g_end[d];
    float adh[H], we[H];
    #pragma unroll
    for (int h = 0; h < H; h++) { adh[h] = g_ad1[d * H + h]; we[h] = g_wed1[h]; }

    float sm[H] = {0, 0, 0, 0, 0}, acc[H] = {0, 0, 0, 0, 0};
    for (int t0 = beg; t0 < end; t0 += 32) {
        int e = t0 + lane;
        int s = 0;
        float ex[H];
        if (e < end) {
            int2 pv = __ldg(&g_ep[e]);
            s = pv.x;
            float eav = __int_as_float(pv.y);
            const float4* ap = (const float4*)&g_as1p[s * 8];
            float4 a0 = __ldg(ap);
            float4 a1 = __ldg(ap + 1);
            float av[H] = {a0.x, a0.y, a0.z, a0.w, a1.x};
            #pragma unroll
            for (int h = 0; h < H; h++) {
                ex[h] = __expf(lrelu(av[h] + adh[h] + eav * we[h]));
                sm[h] += ex[h];
            }
        } else {
            #pragma unroll
            for (int h = 0; h < H; h++) ex[h] = 0.f;
        }
        int cnt = min(32, end - t0);
        for (int j = 0; j < cnt; j++) {
            int   s2 = __shfl_sync(0xffffffffu, s, j);
            float a0 = __shfl_sync(0xffffffffu, ex[0], j);
            float a1 = __shfl_sync(0xffffffffu, ex[1], j);
            float a2 = __shfl_sync(0xffffffffu, ex[2], j);
            float a3 = __shfl_sync(0xffffffffu, ex[3], j);
            float a4 = __shfl_sync(0xffffffffu, ex[4], j);
            uint4 hr = __ldg((const uint4*)&g_h1t[s2 * 256 + lane * 8]); // 1 LDG.128
            float2 f0 = __half22float2(*(const __half2*)&hr.x);
            float2 f1 = __half22float2(*(const __half2*)&hr.y);
            float2 f2 = __half22float2(*(const __half2*)&hr.z);
            acc[0] = fmaf(a0, f0.x, acc[0]);
            acc[1] = fmaf(a1, f0.y, acc[1]);
            acc[2] = fmaf(a2, f1.x, acc[2]);
            acc[3] = fmaf(a3, f1.y, acc[3]);
            acc[4] = fmaf(a4, f2.x, acc[4]);
        }
    }
    #pragma unroll
    for (int h = 0; h < H; h++)
        #pragma unroll
        for (int o = 16; o > 0; o >>= 1)
            sm[h] += __shfl_xor_sync(0xffffffffu, sm[h], o);

    // x2 channels c=h*32+lane kept in registers, fused node2: h2 = x2 @ W2
    float xo[H];
    #pragma unroll
    for (int h = 0; h < H; h++) {
        float inv = 1.f / (sm[h] + 1e-16f);
        xo[h] = fmaxf(acc[h] * inv + __ldg(&b1[h * C1 + lane]), 0.f);
    }
    float hv[H] = {0, 0, 0, 0, 0};
    #pragma unroll
    for (int h = 0; h < H; h++) {
        const float* wr = &W2[(h * C1 + lane) * H];
        #pragma unroll
        for (int h2 = 0; h2 < H; h2++) hv[h2] = fmaf(xo[h], __ldg(&wr[h2]), hv[h2]);
    }
    #pragma unroll
    for (int h2 = 0; h2 < H; h2++)
        #pragma unroll
        for (int o = 16; o > 0; o >>= 1)
            hv[h2] += __shfl_xor_sync(0xffffffffu, hv[h2], o);
    float wv = (lane == 0) ? hv[0] : (lane == 1) ? hv[1] : (lane == 2) ? hv[2]
             : (lane == 3) ? hv[3] : (lane == 4) ? hv[4] : 0.f;
    if (lane < 8) g_h2p[d * 8 + lane] = wv;   // padded row, zeros in 5..7
}

// ---------------- layer 2 aggregation + head-mean + linear + sigmoid ---------
__global__ void __launch_bounds__(256) k_agg2(
        const float* __restrict__ as2p, const float* __restrict__ ad2p,
        const float* __restrict__ b2, const float* __restrict__ Wlin,
        float* __restrict__ out, int N) {
    int gt = blockIdx.x * blockDim.x + threadIdx.x;
    int d = gt >> 5, lane = gt & 31;
    if (d >= N) return;
    int beg = g_beg[d], end = g_end[d];
    const float4* dp = (const float4*)&g_h2p[d * 8];
    float4 q0 = __ldg(dp), q1 = __ldg(dp + 1);
    float hd[H] = {q0.x, q0.y, q0.z, q0.w, q1.x};
    float adh[H], as2[H], we[H];
    #pragma unroll
    for (int h = 0; h < H; h++) {
        adh[h] = hd[h] * __ldg(&ad2p[h]);
        as2[h] = __ldg(&as2p[h]);
        we[h] = g_wed2[h];
    }
    float sm[H] = {0, 0, 0, 0, 0}, ws[H] = {0, 0, 0, 0, 0};
    for (int e = beg + lane; e < end; e += 32) {
        int2 pv = __ldg(&g_ep[e]);
        float eav = __int_as_float(pv.y);
        const float4* sp = (const float4*)&g_h2p[pv.x * 8];
        float4 p0 = __ldg(sp), p1 = __ldg(sp + 1);
        float hs[H] = {p0.x, p0.y, p0.z, p0.w, p1.x};
        #pragma unroll
        for (int h = 0; h < H; h++) {
            float ex = __expf(lrelu(hs[h] * as2[h] + adh[h] + eav * we[h]));
            sm[h] += ex;
            ws[h] = fmaf(ex, hs[h], ws[h]);
        }
    }
    #pragma unroll
    for (int h = 0; h < H; h++)
        #pragma unroll
        for (int o = 16; o > 0; o >>= 1) {
            sm[h] += __shfl_xor_sync(0xffffffffu, sm[h], o);
            ws[h] += __shfl_xor_sync(0xffffffffu, ws[h], o);
        }
    if (lane == 0) {
        float m = 0.f;
        #pragma unroll
        for (int h = 0; h < H; h++) m += ws[h] / (sm[h] + 1e-16f);
        m = m * 0.2f + __ldg(&b2[0]);
        m *= __ldg(&Wlin[0]);
        out[d] = 1.f / (1.f + __expf(-m));
    }
}

// ---------------- launch -----------------------------------------------------
extern "C" void kernel_launch(void* const* d_in, const int* in_sizes, int n_in,
                              void* d_out, int out_size) {
    const float* x     = (const float*)d_in[0];
    const float* eattr = (const float*)d_in[1];
    const int*   src   = (const int*)  d_in[2];
    const int*   dst   = (const int*)  d_in[3];
    const float* W1    = (const float*)d_in[4];
    const float* as1   = (const float*)d_in[5];
    const float* ad1   = (const float*)d_in[6];
    const float* We1   = (const float*)d_in[7];
    const float* ae1   = (const float*)d_in[8];
    const float* b1    = (const float*)d_in[9];
    const float* W2    = (const float*)d_in[10];
    const float* as2   = (const float*)d_in[11];
    const float* ad2   = (const float*)d_in[12];
    const float* We2   = (const float*)d_in[13];
    const float* ae2   = (const float*)d_in[14];
    const float* b2    = (const float*)d_in[15];
    const float* Wlin  = (const float*)d_in[16];
    float* out = (float*)d_out;

    int N = in_sizes[0] / NF;
    int E = in_sizes[2];
    int nbN = (N + 7) / 8;
    int nbE = (E + 255) / 256;

    k_front  <<<nbN + nbE, 256>>>(x, W1, as1, ad1, dst, eattr, N, E, nbN);
    k_alloc  <<<(N + 255) / 256, 256>>>(We1, ae1, We2, ae2, N, E);
    k_scatter<<<(E + N + 255) / 256, 256>>>(src, dst, eattr, E, N);
    k_agg1   <<<(N * 32 + 255) / 256, 256>>>(b1, W2, N);
    k_agg2   <<<(N * 32 + 255) / 256, 256>>>(as2, ad2, b2, Wlin, out, N);
}

// round 16
// speedup vs baseline: 1.5814x; 1.3475x over previous
#include <cuda_runtime.h>
#include <cuda_fp16.h>

#define NN 50000
#define NE 800000
#define TE (NE + NN)
#define H  5
#define C1 32
#define F1 160
#define NF 5

// ---------------- device scratch ---------------------------------------------
__device__ __half g_h1h[NN * F1];    // layer1 node features fp16 [N,160] row-major
__device__ __half g_as1h[NN * 8];    // alpha_src layer1, fp16 padded to 8 (16B row)
__device__ float  g_ad1[NN * H];     // alpha_dst layer1 (per-warp broadcast reads)
__device__ __half g_h2h[NN * 8];     // layer2 node features fp16 padded to 8 (16B row)
__device__ float  g_W2t[H * F1];     // W2 transposed [h2][160] for coalesced epilogue
__device__ int    g_cnt[NN];         // in-degree counts (zeroed by k_alloc each call)
__device__ int    g_beg[NN];         // segment begin
__device__ int    g_end[NN];         // segment end
__device__ int    g_cur[NN];         // scatter cursors
__device__ int2   g_ep[TE];          // packed (src, edge_attr), grouped by dst
__device__ int    g_total;           // atomic allocation base
__device__ float  g_easum;
__device__ float  g_eamean;
__device__ float  g_wed1[H];
__device__ float  g_wed2[H];

__device__ __forceinline__ float lrelu(float x) { return x > 0.f ? x : 0.2f * x; }

// ---------------- fused front: node1 transform (warp/node) + count + easum ---
__global__ void __launch_bounds__(256) k_front(
        const float* __restrict__ x, const float* __restrict__ W1,
        const float* __restrict__ as, const float* __restrict__ ad,
        const int* __restrict__ dst, const float* __restrict__ ea,
        int N, int E, int nbN) {
    int b = blockIdx.x, t = threadIdx.x;
    if (b == 0 && t == 0) g_total = 0;
    if (b < nbN) {
        int n = b * 8 + (t >> 5);
        int lane = t & 31;
        if (n >= N) return;
        float xv[NF];
        #pragma unroll
        for (int f = 0; f < NF; f++) xv[f] = __ldg(&x[n * NF + f]);
        float sarr[H];
        #pragma unroll
        for (int h = 0; h < H; h++) {
            int c = h * C1 + lane;
            float v = 0.f;
            #pragma unroll
            for (int f = 0; f < NF; f++) v = fmaf(xv[f], __ldg(&W1[f * F1 + c]), v);
            g_h1h[n * F1 + c] = __float2half(v);       // row-major fp16 (R12 layout)
            float s = v * __ldg(&as[c]);
            float d = v * __ldg(&ad[c]);
            #pragma unroll
            for (int o = 16; o > 0; o >>= 1) {
                s += __shfl_xor_sync(0xffffffffu, s, o);
                d += __shfl_xor_sync(0xffffffffu, d, o);
            }
            sarr[h] = s;
            if (lane == 0) g_ad1[n * H + h] = d;
        }
        if (lane == 0) {                                // one ST.128: as1 fp16 x8
            union { __half hh[8]; uint4 u; } pk;
            #pragma unroll
            for (int h = 0; h < H; h++) pk.hh[h] = __float2half(sarr[h]);
            pk.hh[5] = pk.hh[6] = pk.hh[7] = __ushort_as_half((unsigned short)0);
            *(uint4*)&g_as1h[n * 8] = pk.u;
        }
    } else {
        __shared__ float sh[256];
        int i = (b - nbN) * 256 + t;
        float v = 0.f;
        if (i < E) { atomicAdd(&g_cnt[dst[i]], 1); v = ea[i]; }
        sh[t] = v;
        __syncthreads();
        for (int o = 128; o > 0; o >>= 1) {
            if (t < o) sh[t] += sh[t + o];
            __syncthreads();
        }
        if (t == 0) atomicAdd(&g_easum, sh[0]);
    }
}

// ---------------- segment allocation: block scan + atomic base ---------------
__global__ void __launch_bounds__(256) k_alloc(
        const float* __restrict__ We1, const float* __restrict__ ae1,
        const float* __restrict__ We2, const float* __restrict__ ae2,
        const float* __restrict__ W2, int N, int E) {
    __shared__ int ws[8], wo[8];
    __shared__ int sbase;
    int b = blockIdx.x, t = threadIdx.x, lane = t & 31, w = t >> 5;
    int i = b * 256 + t;
    int v = (i < N) ? (g_cnt[i] + 1) : 0;   // +1 = self loop
    int sv = v;
    #pragma unroll
    for (int o = 1; o < 32; o <<= 1) {
        int u = __shfl_up_sync(0xffffffffu, sv, o);
        if (lane >= o) sv += u;
    }
    if (lane == 31) ws[w] = sv;
    __syncthreads();
    if (t < 8) {
        int acc = 0;
        for (int j = 0; j < t; j++) acc += ws[j];
        wo[t] = acc;
    }
    __syncthreads();
    if (t == 0) sbase = atomicAdd(&g_total, wo[7] + ws[7]);
    __syncthreads();
    if (i < N) {
        int beg = sbase + wo[w] + sv - v;
        g_beg[i] = beg; g_end[i] = beg + v; g_cur[i] = beg;
        g_cnt[i] = 0;                        // reset for next call
    }
    if (b == 0) {
        // transposed W2 for coalesced epilogue reads: W2t[h2*160 + c] = W2[c*5+h2]
        for (int j = t; j < H * F1; j += 256) {
            int h2 = j / F1, c = j - h2 * F1;
            g_W2t[j] = W2[c * H + h2];
        }
        if (t < H) {
            float a = 0.f;
            for (int c = 0; c < C1; c++) a += We1[t * C1 + c] * ae1[t * C1 + c];
            g_wed1[t] = a;
            g_wed2[t] = We2[t] * ae2[t];
        }
        if (t == 0) { g_eamean = g_easum / (float)E; g_easum = 0.f; }
    }
}

// ---------------- scatter into packed segments -------------------------------
__global__ void k_scatter(const int* __restrict__ src, const int* __restrict__ dst,
                          const float* __restrict__ ea, int E, int N) {
    int i = blockIdx.x * blockDim.x + threadIdx.x;
    if (i < E) {
        int p = atomicAdd(&g_cur[dst[i]], 1);
        g_ep[p] = make_int2(src[i], __float_as_int(ea[i]));
    } else if (i < E + N) {
        int n = i - E;
        int p = atomicAdd(&g_cur[n], 1);
        g_ep[p] = make_int2(n, __float_as_int(g_eamean));
    }
}

// ---------------- layer 1 aggregation: warp per dst (R12 gather structure) ---
// prologue: per-lane edge -> ex[5] (one fp16 LDG.128 for as1); j-loop: SHFL
// broadcast + 5 scalar LDG.U16 from row-major h1 (empirically fastest form).
// epilogue: coalesced W2t reads; fused relu + node2; h2 stored fp16-packed.
__global__ void __launch_bounds__(256) k_agg1(const float* __restrict__ b1, int N) {
    int gt = blockIdx.x * blockDim.x + threadIdx.x;
    int d = gt >> 5, lane = gt & 31;
    if (d >= N) return;
    int beg = g_beg[d], end = g_end[d];
    float adh[H], we[H];
    #pragma unroll
    for (int h = 0; h < H; h++) { adh[h] = g_ad1[d * H + h]; we[h] = g_wed1[h]; }

    float sm[H] = {0, 0, 0, 0, 0}, acc[H] = {0, 0, 0, 0, 0};
    for (int t0 = beg; t0 < end; t0 += 32) {
        int e = t0 + lane;
        int s = 0;
        float ex[H];
        if (e < end) {
            int2 pv = __ldg(&g_ep[e]);
            s = pv.x;
            float eav = __int_as_float(pv.y);
            uint4 au = __ldg((const uint4*)&g_as1h[s * 8]);   // 1 LDG.128 fp16
            float2 a01 = __half22float2(*(const __half2*)&au.x);
            float2 a23 = __half22float2(*(const __half2*)&au.y);
            float2 a4x = __half22float2(*(const __half2*)&au.z);
            float av[H] = {a01.x, a01.y, a23.x, a23.y, a4x.x};
            #pragma unroll
            for (int h = 0; h < H; h++) {
                ex[h] = __expf(lrelu(av[h] + adh[h] + eav * we[h]));
                sm[h] += ex[h];
            }
        } else {
            #pragma unroll
            for (int h = 0; h < H; h++) ex[h] = 0.f;
        }
        int cnt = min(32, end - t0);
        for (int j = 0; j < cnt; j++) {
            int   s2 = __shfl_sync(0xffffffffu, s, j);
            float a0 = __shfl_sync(0xffffffffu, ex[0], j);
            float a1 = __shfl_sync(0xffffffffu, ex[1], j);
            float a2 = __shfl_sync(0xffffffffu, ex[2], j);
            float a3 = __shfl_sync(0xffffffffu, ex[3], j);
            float a4 = __shfl_sync(0xffffffffu, ex[4], j);
            const __half* hp = &g_h1h[s2 * F1 + lane];   // 5 coalesced 64B rows
            acc[0] = fmaf(a0, __half2float(__ldg(&hp[0])),   acc[0]);
            acc[1] = fmaf(a1, __half2float(__ldg(&hp[32])),  acc[1]);
            acc[2] = fmaf(a2, __half2float(__ldg(&hp[64])),  acc[2]);
            acc[3] = fmaf(a3, __half2float(__ldg(&hp[96])),  acc[3]);
            acc[4] = fmaf(a4, __half2float(__ldg(&hp[128])), acc[4]);
        }
    }
    #pragma unroll
    for (int h = 0; h < H; h++)
        #pragma unroll
        for (int o = 16; o > 0; o >>= 1)
            sm[h] += __shfl_xor_sync(0xffffffffu, sm[h], o);

    // x2 channels c=h*32+lane in registers, fused node2 via transposed W2
    float xo[H];
    #pragma unroll
    for (int h = 0; h < H; h++) {
        float inv = 1.f / (sm[h] + 1e-16f);
        xo[h] = fmaxf(acc[h] * inv + __ldg(&b1[h * C1 + lane]), 0.f);
    }
    float hv[H] = {0, 0, 0, 0, 0};
    #pragma unroll
    for (int h2 = 0; h2 < H; h2++) {
        const float* wt = &g_W2t[h2 * F1 + lane];        // coalesced, L1-resident
        #pragma unroll
        for (int h = 0; h < H; h++)
            hv[h2] = fmaf(xo[h], __ldg(&wt[h * C1]), hv[h2]);
    }
    #pragma unroll
    for (int h2 = 0; h2 < H; h2++)
        #pragma unroll
        for (int o = 16; o > 0; o >>= 1)
            hv[h2] += __shfl_xor_sync(0xffffffffu, hv[h2], o);
    if (lane == 0) {                                     // one ST.128: h2 fp16 x8
        union { __half hh[8]; uint4 u; } pk;
        #pragma unroll
        for (int h2 = 0; h2 < H; h2++) pk.hh[h2] = __float2half(hv[h2]);
        pk.hh[5] = pk.hh[6] = pk.hh[7] = __ushort_as_half((unsigned short)0);
        *(uint4*)&g_h2h[d * 8] = pk.u;
    }
}

// ---------------- layer 2 aggregation + head-mean + linear + sigmoid ---------
__global__ void __launch_bounds__(256) k_agg2(
        const float* __restrict__ as2p, const float* __restrict__ ad2p,
        const float* __restrict__ b2, const float* __restrict__ Wlin,
        float* __restrict__ out, int N) {
    int gt = blockIdx.x * blockDim.x + threadIdx.x;
    int d = gt >> 5, lane = gt & 31;
    if (d >= N) return;
    int beg = g_beg[d], end = g_end[d];
    uint4 du = __ldg((const uint4*)&g_h2h[d * 8]);
    float2 d01 = __half22float2(*(const __half2*)&du.x);
    float2 d23 = __half22float2(*(const __half2*)&du.y);
    float2 d4x = __half22float2(*(const __half2*)&du.z);
    float hd[H] = {d01.x, d01.y, d23.x, d23.y, d4x.x};
    float adh[H], as2[H], we[H];
    #pragma unroll
    for (int h = 0; h < H; h++) {
        adh[h] = hd[h] * __ldg(&ad2p[h]);
        as2[h] = __ldg(&as2p[h]);
        we[h] = g_wed2[h];
    }
    float sm[H] = {0, 0, 0, 0, 0}, ws[H] = {0, 0, 0, 0, 0};
    for (int e = beg + lane; e < end; e += 32) {
        int2 pv = __ldg(&g_ep[e]);
        float eav = __int_as_float(pv.y);
        uint4 su = __ldg((const uint4*)&g_h2h[pv.x * 8]);  // 1 LDG.128 fp16
        float2 s01 = __half22float2(*(const __half2*)&su.x);
        float2 s23 = __half22float2(*(const __half2*)&su.y);
        float2 s4x = __half22float2(*(const __half2*)&su.z);
        float hs[H] = {s01.x, s01.y, s23.x, s23.y, s4x.x};
        #pragma unroll
        for (int h = 0; h < H; h++) {
            float ex = __expf(lrelu(hs[h] * as2[h] + adh[h] + eav * we[h]));
            sm[h] += ex;
            ws[h] = fmaf(ex, hs[h], ws[h]);
        }
    }
    #pragma unroll
    for (int h = 0; h < H; h++)
        #pragma unroll
        for (int o = 16; o > 0; o >>= 1) {
            sm[h] += __shfl_xor_sync(0xffffffffu, sm[h], o);
            ws[h] += __shfl_xor_sync(0xffffffffu, ws[h], o);
        }
    if (lane == 0) {
        float m = 0.f;
        #pragma unroll
        for (int h = 0; h < H; h++) m += ws[h] / (sm[h] + 1e-16f);
        m = m * 0.2f + __ldg(&b2[0]);
        m *= __ldg(&Wlin[0]);
        out[d] = 1.f / (1.f + __expf(-m));
    }
}

// ---------------- launch -----------------------------------------------------
extern "C" void kernel_launch(void* const* d_in, const int* in_sizes, int n_in,
                              void* d_out, int out_size) {
    const float* x     = (const float*)d_in[0];
    const float* eattr = (const float*)d_in[1];
    const int*   src   = (const int*)  d_in[2];
    const int*   dst   = (const int*)  d_in[3];
    const float* W1    = (const float*)d_in[4];
    const float* as1   = (const float*)d_in[5];
    const float* ad1   = (const float*)d_in[6];
    const float* We1   = (const float*)d_in[7];
    const float* ae1   = (const float*)d_in[8];
    const float* b1    = (const float*)d_in[9];
    const float* W2    = (const float*)d_in[10];
    const float* as2   = (const float*)d_in[11];
    const float* ad2   = (const float*)d_in[12];
    const float* We2   = (const float*)d_in[13];
    const float* ae2   = (const float*)d_in[14];
    const float* b2    = (const float*)d_in[15];
    const float* Wlin  = (const float*)d_in[16];
    float* out = (float*)d_out;

    int N = in_sizes[0] / NF;
    int E = in_sizes[2];
    int nbN = (N + 7) / 8;
    int nbE = (E + 255) / 256;

    k_front  <<<nbN + nbE, 256>>>(x, W1, as1, ad1, dst, eattr, N, E, nbN);
    k_alloc  <<<(N + 255) / 256, 256>>>(We1, ae1, We2, ae2, W2, N, E);
    k_scatter<<<(E + N + 255) / 256, 256>>>(src, dst, eattr, E, N);
    k_agg1   <<<(N * 32 + 255) / 256, 256>>>(b1, N);
    k_agg2   <<<(N * 32 + 255) / 256, 256>>>(as2, ad2, b2, Wlin, out, N);
}